// round 9
// baseline (speedup 1.0000x reference)
#include <cuda_runtime.h>
#include <math.h>

// Problem constants (from reference)
constexpr int Nn  = 100000;
constexpr int Ee  = 3200000;
constexpr int ET  = Nn + Ee;       // edges + self loops
constexpr int FIN = 165;
constexpr int HID = 64;

// ---------------- scratch (static device allocations; no cudaMalloc) ----------------
__device__ float g_xl1[(size_t)Nn * HID];
__device__ float g_xr1[(size_t)Nn * HID];
__device__ float g_h  [(size_t)Nn * HID];   // x@Wlin1+blin1, then final layer-1 hidden
__device__ float g_xl2[Nn * 2];
__device__ float g_xr2[Nn * 2];
__device__ float g_lin2[Nn * 2];
__device__ int   g_deg[Nn];
__device__ int   g_incl[Nn];
__device__ int   g_rowptr[Nn + 1];
__device__ int   g_cursor[Nn];
__device__ int   g_bsum[128];
__device__ int   g_boff[128];
__device__ int   g_col[ET];

// ---------------- K0: init degrees (self loop => start at 1) ----------------
__global__ void k_init_deg() {
    int i = blockIdx.x * blockDim.x + threadIdx.x;
    if (i < Nn) g_deg[i] = 1;
}

// ---------------- K1: fused layer-1 triple GEMM (R5 version — measured best) ----------------
constexpr int G1_THREADS = 384;                 // 24 col-threads x 16 node-threads
constexpr int G1_SMEM = (FIN * 192 + 64 * FIN) * 4;   // 168,960 B

__global__ __launch_bounds__(G1_THREADS, 1)
void k_gemm1(const float* __restrict__ x,
             const float* __restrict__ Wl, const float* __restrict__ Wr,
             const float* __restrict__ Wlin, const float* __restrict__ blin) {
    extern __shared__ float sm[];
    float* Wsh = sm;                  // [165][192]
    float* Xsh = sm + FIN * 192;      // [64][165]
    int tid = threadIdx.x;

    for (int idx = tid; idx < FIN * 192; idx += G1_THREADS) {
        int k = idx / 192, c = idx % 192;
        float v = (c < 64) ? Wl[k * 64 + c]
                : (c < 128) ? Wr[k * 64 + (c - 64)]
                : Wlin[k * 64 + (c - 128)];
        Wsh[idx] = v;
    }
    __syncthreads();

    int ct = tid % 24;                // col group: 8 cols each
    int nt = tid / 24;                // node group: 4 nodes each (nt 0..15)
    int cbase = ct * 8;
    int region = cbase >> 6;          // 0: xl1, 1: xr1, 2: lin
    int coff = cbase & 63;

    float bias_r[8];
#pragma unroll
    for (int q = 0; q < 8; q++) bias_r[q] = (region == 2) ? blin[coff + q] : 0.0f;

    const float4* W4 = (const float4*)Wsh;
    constexpr int NTILES = (Nn + 63) / 64;   // 1563 (last tile has 32 rows)

    for (int tile = blockIdx.x; tile < NTILES; tile += gridDim.x) {
        int row0 = tile * 64;
        int rows = (Nn - row0 < 64) ? (Nn - row0) : 64;
        const float4* xsrc = (const float4*)(x + (size_t)row0 * FIN);
        float4* xdst = (float4*)Xsh;
        int nload = (rows * FIN) / 4;
        for (int idx = tid; idx < nload; idx += G1_THREADS) xdst[idx] = xsrc[idx];
        __syncthreads();

        float acc[4][8];
#pragma unroll
        for (int n = 0; n < 4; n++)
#pragma unroll
            for (int q = 0; q < 8; q++) acc[n][q] = 0.0f;

        const float* xr0 = Xsh + (nt * 4 + 0) * FIN;
        const float* xr1 = Xsh + (nt * 4 + 1) * FIN;
        const float* xr2 = Xsh + (nt * 4 + 2) * FIN;
        const float* xr3 = Xsh + (nt * 4 + 3) * FIN;

#pragma unroll 3
        for (int k = 0; k < FIN; k++) {
            float x0 = xr0[k], x1 = xr1[k], x2 = xr2[k], x3 = xr3[k];
            float4 wA = W4[k * 48 + ct * 2];
            float4 wB = W4[k * 48 + ct * 2 + 1];
            acc[0][0] += x0 * wA.x; acc[0][1] += x0 * wA.y;
            acc[0][2] += x0 * wA.z; acc[0][3] += x0 * wA.w;
            acc[0][4] += x0 * wB.x; acc[0][5] += x0 * wB.y;
            acc[0][6] += x0 * wB.z; acc[0][7] += x0 * wB.w;
            acc[1][0] += x1 * wA.x; acc[1][1] += x1 * wA.y;
            acc[1][2] += x1 * wA.z; acc[1][3] += x1 * wA.w;
            acc[1][4] += x1 * wB.x; acc[1][5] += x1 * wB.y;
            acc[1][6] += x1 * wB.z; acc[1][7] += x1 * wB.w;
            acc[2][0] += x2 * wA.x; acc[2][1] += x2 * wA.y;
            acc[2][2] += x2 * wA.z; acc[2][3] += x2 * wA.w;
            acc[2][4] += x2 * wB.x; acc[2][5] += x2 * wB.y;
            acc[2][6] += x2 * wB.z; acc[2][7] += x2 * wB.w;
            acc[3][0] += x3 * wA.x; acc[3][1] += x3 * wA.y;
            acc[3][2] += x3 * wA.z; acc[3][3] += x3 * wA.w;
            acc[3][4] += x3 * wB.x; acc[3][5] += x3 * wB.y;
            acc[3][6] += x3 * wB.z; acc[3][7] += x3 * wB.w;
        }

#pragma unroll
        for (int n = 0; n < 4; n++) {
            int ng = row0 + nt * 4 + n;
            if (ng < Nn) {
                float* base = (region == 0) ? g_xl1 : (region == 1) ? g_xr1 : g_h;
                base += (size_t)ng * 64 + coff;
                float4 v0 = make_float4(acc[n][0] + bias_r[0], acc[n][1] + bias_r[1],
                                        acc[n][2] + bias_r[2], acc[n][3] + bias_r[3]);
                float4 v1 = make_float4(acc[n][4] + bias_r[4], acc[n][5] + bias_r[5],
                                        acc[n][6] + bias_r[6], acc[n][7] + bias_r[7]);
                ((float4*)base)[0] = v0;
                ((float4*)base)[1] = v1;
            }
        }
        __syncthreads();
    }
}

// ---------------- K2: degree histogram over real edges ----------------
__global__ void k_deg(const int* __restrict__ ei) {
    int i = blockIdx.x * blockDim.x + threadIdx.x;
    if (i < Ee) {
        int d = ei[Ee + i];     // dst row
        atomicAdd(&g_deg[d], 1);
    }
}

// ---------------- K3: 3-phase exclusive scan -> rowptr, cursor ----------------
__global__ __launch_bounds__(1024) void k_scan1() {
    __shared__ int s[1024];
    int tid = threadIdx.x;
    int i = blockIdx.x * 1024 + tid;
    int v = (i < Nn) ? g_deg[i] : 0;
    s[tid] = v;
    __syncthreads();
    for (int off = 1; off < 1024; off <<= 1) {
        int t = (tid >= off) ? s[tid - off] : 0;
        __syncthreads();
        s[tid] += t;
        __syncthreads();
    }
    if (i < Nn) g_incl[i] = s[tid];
    if (tid == 1023) g_bsum[blockIdx.x] = s[tid];
}

__global__ void k_scan2(int nb) {
    __shared__ int s[128];
    int tid = threadIdx.x;
    int v = (tid < nb) ? g_bsum[tid] : 0;
    s[tid] = v;
    __syncthreads();
    for (int off = 1; off < 128; off <<= 1) {
        int t = (tid >= off) ? s[tid - off] : 0;
        __syncthreads();
        s[tid] += t;
        __syncthreads();
    }
    g_boff[tid] = s[tid] - v;   // exclusive
}

__global__ void k_scan3() {
    int i = blockIdx.x * blockDim.x + threadIdx.x;
    if (i < Nn) {
        int r = g_incl[i] + g_boff[i >> 10];
        g_rowptr[i + 1] = r;
        g_cursor[i] = r - g_deg[i];    // == rowptr[i]
        if (i == 0) g_rowptr[0] = 0;
    }
}

// ---------------- K4: scatter edges + self loops into CSR ----------------
__global__ void k_scatter(const int* __restrict__ ei) {
    int i = blockIdx.x * blockDim.x + threadIdx.x;
    if (i >= ET) return;
    int s, d;
    if (i < Ee) { s = ei[i]; d = ei[Ee + i]; }
    else        { s = d = i - Ee; }
    int pos = atomicAdd(&g_cursor[d], 1);
    g_col[pos] = s;
}

// ---------------- K5: layer-1 attention — 4 edge-slots x 8 channel-lanes ----------------
// Warp per node. lane = e*8+g: slot e handles edges idx≡e (mod 4); lane owns
// channels [g*8, g*8+8). Dot reduces in 3 shuffles per 4 edges; per-slot online
// softmax states merge with 2 rescaling butterfly levels at the end.
__global__ void k_att1(const float* __restrict__ att, const float* __restrict__ b1) {
    int gt = blockIdx.x * blockDim.x + threadIdx.x;
    int i = gt >> 5;
    int lane = gt & 31;
    if (i >= Nn) return;
    int e = lane >> 3;        // edge slot 0..3
    int g = lane & 7;         // channel group

    int e0 = g_rowptr[i], e1 = g_rowptr[i + 1];

    const float4* xr4 = (const float4*)(g_xr1 + (size_t)i * 64);
    float4 rA = xr4[g * 2], rB = xr4[g * 2 + 1];
    const float4* a4 = (const float4*)att;
    float4 aA = a4[g * 2], aB = a4[g * 2 + 1];

    float m = -1e30f, s = 0.f;
    float A[8] = {0, 0, 0, 0, 0, 0, 0, 0};

    for (int base = e0; base < e1; base += 4) {
        int idx = base + e;
        bool act = idx < e1;
        int j = act ? g_col[idx] : 0;
        const float4* u4 = (const float4*)(g_xl1 + (size_t)j * 64);
        float4 uA = u4[g * 2], uB = u4[g * 2 + 1];

        float t0 = uA.x + rA.x; t0 = (t0 > 0.f) ? t0 : 0.2f * t0;
        float t1 = uA.y + rA.y; t1 = (t1 > 0.f) ? t1 : 0.2f * t1;
        float t2 = uA.z + rA.z; t2 = (t2 > 0.f) ? t2 : 0.2f * t2;
        float t3 = uA.w + rA.w; t3 = (t3 > 0.f) ? t3 : 0.2f * t3;
        float t4 = uB.x + rB.x; t4 = (t4 > 0.f) ? t4 : 0.2f * t4;
        float t5 = uB.y + rB.y; t5 = (t5 > 0.f) ? t5 : 0.2f * t5;
        float t6 = uB.z + rB.z; t6 = (t6 > 0.f) ? t6 : 0.2f * t6;
        float t7 = uB.w + rB.w; t7 = (t7 > 0.f) ? t7 : 0.2f * t7;
        float p = t0 * aA.x + t1 * aA.y + t2 * aA.z + t3 * aA.w
                + t4 * aB.x + t5 * aB.y + t6 * aB.z + t7 * aB.w;
        // reduce over the 8 lanes of this slot (xor 1,2,4 stays in-group)
        p += __shfl_xor_sync(0xffffffffu, p, 1);
        p += __shfl_xor_sync(0xffffffffu, p, 2);
        p += __shfl_xor_sync(0xffffffffu, p, 4);

        if (act) {
            if (p > m) {
                float sc = __expf(m - p);
                s *= sc;
#pragma unroll
                for (int q = 0; q < 8; q++) A[q] *= sc;
                m = p;
            }
            float w = __expf(p - m);
            s += w;
            A[0] += w * uA.x; A[1] += w * uA.y; A[2] += w * uA.z; A[3] += w * uA.w;
            A[4] += w * uB.x; A[5] += w * uB.y; A[6] += w * uB.z; A[7] += w * uB.w;
        }
    }

    // merge the 4 slot-states (xor 8, xor 16 cross e with same g)
#pragma unroll
    for (int o = 8; o <= 16; o <<= 1) {
        float mo = __shfl_xor_sync(0xffffffffu, m, o);
        float so = __shfl_xor_sync(0xffffffffu, s, o);
        float Ao[8];
#pragma unroll
        for (int q = 0; q < 8; q++) Ao[q] = __shfl_xor_sync(0xffffffffu, A[q], o);
        float mn = fmaxf(m, mo);
        float c1 = __expf(m - mn);
        float c2 = __expf(mo - mn);
        s = s * c1 + so * c2;
#pragma unroll
        for (int q = 0; q < 8; q++) A[q] = A[q] * c1 + Ao[q] * c2;
        m = mn;
    }

    if (e == 0) {
        float inv = 1.0f / s;
        const float4* b4 = (const float4*)b1;
        float4 bA = b4[g * 2], bB = b4[g * 2 + 1];
        float4* h4 = (float4*)(g_h + (size_t)i * 64);
        float4 hA = h4[g * 2], hB = h4[g * 2 + 1];
        float o0 = A[0] * inv + bA.x + hA.x;
        float o1 = A[1] * inv + bA.y + hA.y;
        float o2 = A[2] * inv + bA.z + hA.z;
        float o3 = A[3] * inv + bA.w + hA.w;
        float o4 = A[4] * inv + bB.x + hB.x;
        float o5 = A[5] * inv + bB.y + hB.y;
        float o6 = A[6] * inv + bB.z + hB.z;
        float o7 = A[7] * inv + bB.w + hB.w;
        o0 = (o0 > 0.f) ? o0 : (__expf(o0) - 1.0f);
        o1 = (o1 > 0.f) ? o1 : (__expf(o1) - 1.0f);
        o2 = (o2 > 0.f) ? o2 : (__expf(o2) - 1.0f);
        o3 = (o3 > 0.f) ? o3 : (__expf(o3) - 1.0f);
        o4 = (o4 > 0.f) ? o4 : (__expf(o4) - 1.0f);
        o5 = (o5 > 0.f) ? o5 : (__expf(o5) - 1.0f);
        o6 = (o6 > 0.f) ? o6 : (__expf(o6) - 1.0f);
        o7 = (o7 > 0.f) ? o7 : (__expf(o7) - 1.0f);
        h4[g * 2]     = make_float4(o0, o1, o2, o3);
        h4[g * 2 + 1] = make_float4(o4, o5, o6, o7);
    }
}

// ---------------- K6: layer-2 transforms (xl2, xr2, lin2) ----------------
__global__ void k_l2xform(const float* __restrict__ Wl2, const float* __restrict__ Wr2,
                          const float* __restrict__ Wlin2, const float* __restrict__ blin2) {
    __shared__ float Ws[384];  // [0:128) Wl2, [128:256) Wr2, [256:384) Wlin2
    int tid = threadIdx.x;
    Ws[tid] = Wl2[tid & 127];               // blockDim = 128
    Ws[128 + tid] = Wr2[tid & 127];
    Ws[256 + tid] = Wlin2[tid & 127];
    __syncthreads();
    int i = blockIdx.x * 128 + tid;
    if (i >= Nn) return;
    float al0 = 0, al1 = 0, ar0 = 0, ar1 = 0, an0 = 0, an1 = 0;
    const float4* h4 = (const float4*)(g_h + (size_t)i * 64);
#pragma unroll
    for (int q = 0; q < 16; q++) {
        float4 hv = h4[q];
        int k = q * 4;
        float c[4] = {hv.x, hv.y, hv.z, hv.w};
#pragma unroll
        for (int t = 0; t < 4; t++) {
            int kk = k + t;
            al0 += c[t] * Ws[2 * kk];       al1 += c[t] * Ws[2 * kk + 1];
            ar0 += c[t] * Ws[128 + 2 * kk]; ar1 += c[t] * Ws[128 + 2 * kk + 1];
            an0 += c[t] * Ws[256 + 2 * kk]; an1 += c[t] * Ws[256 + 2 * kk + 1];
        }
    }
    ((float2*)g_xl2)[i] = make_float2(al0, al1);
    ((float2*)g_xr2)[i] = make_float2(ar0, ar1);
    ((float2*)g_lin2)[i] = make_float2(an0 + blin2[0], an1 + blin2[1]);
}

// ---------------- K7: layer-2 attention, SINGLE PASS + log_softmax ----------------
__global__ void k_att2(const float* __restrict__ att2, const float* __restrict__ b2,
                       float* __restrict__ out) {
    int gt = blockIdx.x * blockDim.x + threadIdx.x;
    int i = gt >> 5;
    int lane = gt & 31;
    if (i >= Nn) return;

    int e0 = g_rowptr[i], e1 = g_rowptr[i + 1];
    const float2* xl2v = (const float2*)g_xl2;
    float2 xr = ((const float2*)g_xr2)[i];
    float a0 = att2[0], a1 = att2[1];

    float m = -1e30f, s = 0.f, A0 = 0.f, A1 = 0.f;
    for (int base = e0; base < e1; base += 32) {
        int idx = base + lane;
        if (idx < e1) {
            int j = g_col[idx];
            float2 xj = xl2v[j];
            float h0 = xj.x + xr.x; h0 = (h0 > 0.f) ? h0 : 0.2f * h0;
            float h1 = xj.y + xr.y; h1 = (h1 > 0.f) ? h1 : 0.2f * h1;
            float e = a0 * h0 + a1 * h1;
            if (e > m) { float sc = __expf(m - e); s *= sc; A0 *= sc; A1 *= sc; m = e; }
            float w = __expf(e - m);
            s += w; A0 += w * xj.x; A1 += w * xj.y;
        }
    }
    // merge lanes with rescale
#pragma unroll
    for (int o = 16; o; o >>= 1) {
        float mo  = __shfl_xor_sync(0xffffffffu, m, o);
        float so  = __shfl_xor_sync(0xffffffffu, s, o);
        float A0o = __shfl_xor_sync(0xffffffffu, A0, o);
        float A1o = __shfl_xor_sync(0xffffffffu, A1, o);
        float mn = fmaxf(m, mo);
        float sc1 = __expf(m - mn);
        float sc2 = __expf(mo - mn);
        s  = s * sc1 + so * sc2;
        A0 = A0 * sc1 + A0o * sc2;
        A1 = A1 * sc1 + A1o * sc2;
        m = mn;
    }

    if (lane == 0) {
        float inv = 1.0f / s;
        float2 ln = ((const float2*)g_lin2)[i];
        float z0 = A0 * inv + b2[0] + ln.x;
        float z1 = A1 * inv + b2[1] + ln.y;
        float zm = fmaxf(z0, z1);
        float l = zm + __logf(__expf(z0 - zm) + __expf(z1 - zm));
        ((float2*)out)[i] = make_float2(z0 - l, z1 - l);
    }
}

// ---------------- K8: edge_index passthrough as float32 values ----------------
__global__ void k_cast_edges(const int* __restrict__ ei, float* __restrict__ out, int n) {
    int i = blockIdx.x * blockDim.x + threadIdx.x;
    if (i < n) out[i] = (float)ei[i];
}

// ---------------- launcher: fork GEMM chain || CSR chain, join before att1 ----------------
extern "C" void kernel_launch(void* const* d_in, const int* in_sizes, int n_in,
                              void* d_out, int out_size) {
    const float* x        = (const float*)d_in[0];
    const float* Wl1      = (const float*)d_in[2];
    const float* Wr1      = (const float*)d_in[3];
    const float* att1     = (const float*)d_in[4];
    const float* b1       = (const float*)d_in[5];
    const float* Wlin1    = (const float*)d_in[6];
    const float* blin1    = (const float*)d_in[7];
    const float* Wl2      = (const float*)d_in[8];
    const float* Wr2      = (const float*)d_in[9];
    const float* att2     = (const float*)d_in[10];
    const float* b2       = (const float*)d_in[11];
    const float* Wlin2    = (const float*)d_in[12];
    const float* blin2    = (const float*)d_in[13];
    float* out = (float*)d_out;

    long long tail_elems = (long long)out_size - (long long)Nn * 2;

    cudaFuncSetAttribute(k_gemm1, cudaFuncAttributeMaxDynamicSharedMemorySize, G1_SMEM);

    int nb = (Nn + 1023) / 1024;   // 98

    // Fork a side stream for the GEMM (independent of CSR build).
    cudaStream_t s2;
    cudaStreamCreateWithFlags(&s2, cudaStreamNonBlocking);
    cudaEvent_t evFork, evJoin;
    cudaEventCreateWithFlags(&evFork, cudaEventDisableTiming);
    cudaEventCreateWithFlags(&evJoin, cudaEventDisableTiming);

    cudaEventRecord(evFork, 0);
    cudaStreamWaitEvent(s2, evFork, 0);

    // side stream: the big dense transform only (critical-path minimal)
    k_gemm1<<<152, G1_THREADS, G1_SMEM, s2>>>(x, Wl1, Wr1, Wlin1, blin1);
    cudaEventRecord(evJoin, s2);

    // main stream: CSR build chain, then output tail (both shadowed by gemm1)
    k_init_deg<<<(Nn + 255) / 256, 256>>>();
    k_deg<<<(Ee + 255) / 256, 256>>>((const int*)d_in[1]);
    k_scan1<<<nb, 1024>>>();
    k_scan2<<<1, 128>>>(nb);
    k_scan3<<<(Nn + 255) / 256, 256>>>();
    k_scatter<<<(ET + 255) / 256, 256>>>((const int*)d_in[1]);
    if (tail_elems > 0) {
        int n = (tail_elems < (long long)2 * Ee) ? (int)tail_elems : 2 * Ee;
        k_cast_edges<<<(n + 255) / 256, 256>>>(
            (const int*)d_in[1], out + (size_t)Nn * 2, n);
    }

    // join: attention needs both GEMM outputs and CSR
    cudaStreamWaitEvent(0, evJoin, 0);
    k_att1<<<(Nn * 32 + 255) / 256, 256>>>(att1, b1);
    k_l2xform<<<(Nn + 127) / 128, 128>>>(Wl2, Wr2, Wlin2, blin2);
    k_att2<<<(Nn * 32 + 255) / 256, 256>>>(att2, b2, out);

    cudaEventDestroy(evFork);
    cudaEventDestroy(evJoin);
    cudaStreamDestroy(s2);
}

// round 10
// speedup vs baseline: 1.4613x; 1.4613x over previous
#include <cuda_runtime.h>
#include <math.h>

// Problem constants (from reference)
constexpr int Nn  = 100000;
constexpr int Ee  = 3200000;
constexpr int ET  = Nn + Ee;       // edges + self loops
constexpr int FIN = 165;
constexpr int HID = 64;

// ---------------- scratch (static device allocations; no cudaMalloc) ----------------
__device__ float g_xl1[(size_t)Nn * HID];
__device__ float g_xr1[(size_t)Nn * HID];
__device__ float g_h  [(size_t)Nn * HID];   // x@Wlin1+blin1, then final layer-1 hidden
__device__ float g_xl2[Nn * 2];
__device__ float g_xr2[Nn * 2];
__device__ float g_lin2[Nn * 2];
__device__ int   g_deg[Nn];
__device__ int   g_incl[Nn];
__device__ int   g_rowptr[Nn + 1];
__device__ int   g_cursor[Nn];
__device__ int   g_bsum[128];
__device__ int   g_boff[128];
__device__ int   g_col[ET];

// ---------------- K0: init degrees (self loop => start at 1) ----------------
__global__ void k_init_deg() {
    int i = blockIdx.x * blockDim.x + threadIdx.x;
    if (i < Nn) g_deg[i] = 1;
}

// ---------------- K1: fused layer-1 triple GEMM (R5 version — measured best) ----------------
constexpr int G1_THREADS = 384;                 // 24 col-threads x 16 node-threads
constexpr int G1_SMEM = (FIN * 192 + 64 * FIN) * 4;   // 168,960 B

__global__ __launch_bounds__(G1_THREADS, 1)
void k_gemm1(const float* __restrict__ x,
             const float* __restrict__ Wl, const float* __restrict__ Wr,
             const float* __restrict__ Wlin, const float* __restrict__ blin) {
    extern __shared__ float sm[];
    float* Wsh = sm;                  // [165][192]
    float* Xsh = sm + FIN * 192;      // [64][165]
    int tid = threadIdx.x;

    for (int idx = tid; idx < FIN * 192; idx += G1_THREADS) {
        int k = idx / 192, c = idx % 192;
        float v = (c < 64) ? Wl[k * 64 + c]
                : (c < 128) ? Wr[k * 64 + (c - 64)]
                : Wlin[k * 64 + (c - 128)];
        Wsh[idx] = v;
    }
    __syncthreads();

    int ct = tid % 24;                // col group: 8 cols each
    int nt = tid / 24;                // node group: 4 nodes each (nt 0..15)
    int cbase = ct * 8;
    int region = cbase >> 6;          // 0: xl1, 1: xr1, 2: lin
    int coff = cbase & 63;

    float bias_r[8];
#pragma unroll
    for (int q = 0; q < 8; q++) bias_r[q] = (region == 2) ? blin[coff + q] : 0.0f;

    const float4* W4 = (const float4*)Wsh;
    constexpr int NTILES = (Nn + 63) / 64;   // 1563 (last tile has 32 rows)

    for (int tile = blockIdx.x; tile < NTILES; tile += gridDim.x) {
        int row0 = tile * 64;
        int rows = (Nn - row0 < 64) ? (Nn - row0) : 64;
        const float4* xsrc = (const float4*)(x + (size_t)row0 * FIN);
        float4* xdst = (float4*)Xsh;
        int nload = (rows * FIN) / 4;
        for (int idx = tid; idx < nload; idx += G1_THREADS) xdst[idx] = xsrc[idx];
        __syncthreads();

        float acc[4][8];
#pragma unroll
        for (int n = 0; n < 4; n++)
#pragma unroll
            for (int q = 0; q < 8; q++) acc[n][q] = 0.0f;

        const float* xr0 = Xsh + (nt * 4 + 0) * FIN;
        const float* xr1 = Xsh + (nt * 4 + 1) * FIN;
        const float* xr2 = Xsh + (nt * 4 + 2) * FIN;
        const float* xr3 = Xsh + (nt * 4 + 3) * FIN;

#pragma unroll 3
        for (int k = 0; k < FIN; k++) {
            float x0 = xr0[k], x1 = xr1[k], x2 = xr2[k], x3 = xr3[k];
            float4 wA = W4[k * 48 + ct * 2];
            float4 wB = W4[k * 48 + ct * 2 + 1];
            acc[0][0] += x0 * wA.x; acc[0][1] += x0 * wA.y;
            acc[0][2] += x0 * wA.z; acc[0][3] += x0 * wA.w;
            acc[0][4] += x0 * wB.x; acc[0][5] += x0 * wB.y;
            acc[0][6] += x0 * wB.z; acc[0][7] += x0 * wB.w;
            acc[1][0] += x1 * wA.x; acc[1][1] += x1 * wA.y;
            acc[1][2] += x1 * wA.z; acc[1][3] += x1 * wA.w;
            acc[1][4] += x1 * wB.x; acc[1][5] += x1 * wB.y;
            acc[1][6] += x1 * wB.z; acc[1][7] += x1 * wB.w;
            acc[2][0] += x2 * wA.x; acc[2][1] += x2 * wA.y;
            acc[2][2] += x2 * wA.z; acc[2][3] += x2 * wA.w;
            acc[2][4] += x2 * wB.x; acc[2][5] += x2 * wB.y;
            acc[2][6] += x2 * wB.z; acc[2][7] += x2 * wB.w;
            acc[3][0] += x3 * wA.x; acc[3][1] += x3 * wA.y;
            acc[3][2] += x3 * wA.z; acc[3][3] += x3 * wA.w;
            acc[3][4] += x3 * wB.x; acc[3][5] += x3 * wB.y;
            acc[3][6] += x3 * wB.z; acc[3][7] += x3 * wB.w;
        }

#pragma unroll
        for (int n = 0; n < 4; n++) {
            int ng = row0 + nt * 4 + n;
            if (ng < Nn) {
                float* base = (region == 0) ? g_xl1 : (region == 1) ? g_xr1 : g_h;
                base += (size_t)ng * 64 + coff;
                float4 v0 = make_float4(acc[n][0] + bias_r[0], acc[n][1] + bias_r[1],
                                        acc[n][2] + bias_r[2], acc[n][3] + bias_r[3]);
                float4 v1 = make_float4(acc[n][4] + bias_r[4], acc[n][5] + bias_r[5],
                                        acc[n][6] + bias_r[6], acc[n][7] + bias_r[7]);
                ((float4*)base)[0] = v0;
                ((float4*)base)[1] = v1;
            }
        }
        __syncthreads();
    }
}

// ---------------- K2: degree histogram over real edges ----------------
__global__ void k_deg(const int* __restrict__ ei) {
    int i = blockIdx.x * blockDim.x + threadIdx.x;
    if (i < Ee) {
        int d = ei[Ee + i];     // dst row
        atomicAdd(&g_deg[d], 1);
    }
}

// ---------------- K3: 3-phase exclusive scan -> rowptr, cursor ----------------
__global__ __launch_bounds__(1024) void k_scan1() {
    __shared__ int s[1024];
    int tid = threadIdx.x;
    int i = blockIdx.x * 1024 + tid;
    int v = (i < Nn) ? g_deg[i] : 0;
    s[tid] = v;
    __syncthreads();
    for (int off = 1; off < 1024; off <<= 1) {
        int t = (tid >= off) ? s[tid - off] : 0;
        __syncthreads();
        s[tid] += t;
        __syncthreads();
    }
    if (i < Nn) g_incl[i] = s[tid];
    if (tid == 1023) g_bsum[blockIdx.x] = s[tid];
}

__global__ void k_scan2(int nb) {
    __shared__ int s[128];
    int tid = threadIdx.x;
    int v = (tid < nb) ? g_bsum[tid] : 0;
    s[tid] = v;
    __syncthreads();
    for (int off = 1; off < 128; off <<= 1) {
        int t = (tid >= off) ? s[tid - off] : 0;
        __syncthreads();
        s[tid] += t;
        __syncthreads();
    }
    g_boff[tid] = s[tid] - v;   // exclusive
}

__global__ void k_scan3() {
    int i = blockIdx.x * blockDim.x + threadIdx.x;
    if (i < Nn) {
        int r = g_incl[i] + g_boff[i >> 10];
        g_rowptr[i + 1] = r;
        g_cursor[i] = r - g_deg[i];    // == rowptr[i]
        if (i == 0) g_rowptr[0] = 0;
    }
}

// ---------------- K4: scatter edges + self loops into CSR ----------------
__global__ void k_scatter(const int* __restrict__ ei) {
    int i = blockIdx.x * blockDim.x + threadIdx.x;
    if (i >= ET) return;
    int s, d;
    if (i < Ee) { s = ei[i]; d = ei[Ee + i]; }
    else        { s = d = i - Ee; }
    int pos = atomicAdd(&g_cursor[d], 1);
    g_col[pos] = s;
}

// ---------------- K5: layer-1 attention — half-warp slots (2 edges/iter) ----------------
// Warp per node. lane = half*16+g: half h handles edges idx≡h (mod 2); lane owns
// channels [g*4, g*4+4) (one float4 → single LDG.128 per 2 edges warp-wide).
// Dot reduces in 4 shuffles per 2 edges (2/edge vs 5/edge in R7). Per-half online
// softmax states merge with ONE rescaling xor-16 level at the end. ~30 regs.
__global__ void k_att1(const float* __restrict__ att, const float* __restrict__ b1) {
    int gt = blockIdx.x * blockDim.x + threadIdx.x;
    int i = gt >> 5;
    int lane = gt & 31;
    if (i >= Nn) return;
    int half = lane >> 4;     // edge slot 0/1
    int g = lane & 15;        // channel group (4 channels)

    int e0 = g_rowptr[i], e1 = g_rowptr[i + 1];

    float4 r = ((const float4*)(g_xr1 + (size_t)i * 64))[g];
    float4 a = ((const float4*)att)[g];

    float m = -1e30f, s = 0.f;
    float A0 = 0.f, A1 = 0.f, A2 = 0.f, A3 = 0.f;

    for (int base = e0; base < e1; base += 2) {
        int idx = base + half;
        bool act = idx < e1;
        int j = act ? g_col[idx] : 0;
        float4 u = ((const float4*)(g_xl1 + (size_t)j * 64))[g];

        float t0 = u.x + r.x; t0 = (t0 > 0.f) ? t0 : 0.2f * t0;
        float t1 = u.y + r.y; t1 = (t1 > 0.f) ? t1 : 0.2f * t1;
        float t2 = u.z + r.z; t2 = (t2 > 0.f) ? t2 : 0.2f * t2;
        float t3 = u.w + r.w; t3 = (t3 > 0.f) ? t3 : 0.2f * t3;
        float p = t0 * a.x + t1 * a.y + t2 * a.z + t3 * a.w;
        // reduce within the 16-lane half (xor 1,2,4,8 keeps bit 4)
        p += __shfl_xor_sync(0xffffffffu, p, 1);
        p += __shfl_xor_sync(0xffffffffu, p, 2);
        p += __shfl_xor_sync(0xffffffffu, p, 4);
        p += __shfl_xor_sync(0xffffffffu, p, 8);

        if (act) {
            if (p > m) {
                float sc = __expf(m - p);
                s *= sc; A0 *= sc; A1 *= sc; A2 *= sc; A3 *= sc;
                m = p;
            }
            float w = __expf(p - m);
            s += w;
            A0 += w * u.x; A1 += w * u.y; A2 += w * u.z; A3 += w * u.w;
        }
    }

    // merge the two half-states (xor 16; same g, other half)
    {
        float mo  = __shfl_xor_sync(0xffffffffu, m, 16);
        float so  = __shfl_xor_sync(0xffffffffu, s, 16);
        float B0  = __shfl_xor_sync(0xffffffffu, A0, 16);
        float B1  = __shfl_xor_sync(0xffffffffu, A1, 16);
        float B2  = __shfl_xor_sync(0xffffffffu, A2, 16);
        float B3  = __shfl_xor_sync(0xffffffffu, A3, 16);
        float mn = fmaxf(m, mo);
        float c1 = __expf(m - mn);
        float c2 = __expf(mo - mn);
        s  = s * c1 + so * c2;
        A0 = A0 * c1 + B0 * c2;
        A1 = A1 * c1 + B1 * c2;
        A2 = A2 * c1 + B2 * c2;
        A3 = A3 * c1 + B3 * c2;
        m = mn;
    }

    if (half == 0) {
        float inv = 1.0f / s;
        float4 bb = ((const float4*)b1)[g];
        float4* h4 = (float4*)(g_h + (size_t)i * 64);
        float4 hl = h4[g];
        float o0 = A0 * inv + bb.x + hl.x;
        float o1 = A1 * inv + bb.y + hl.y;
        float o2 = A2 * inv + bb.z + hl.z;
        float o3 = A3 * inv + bb.w + hl.w;
        o0 = (o0 > 0.f) ? o0 : (__expf(o0) - 1.0f);   // ELU
        o1 = (o1 > 0.f) ? o1 : (__expf(o1) - 1.0f);
        o2 = (o2 > 0.f) ? o2 : (__expf(o2) - 1.0f);
        o3 = (o3 > 0.f) ? o3 : (__expf(o3) - 1.0f);
        h4[g] = make_float4(o0, o1, o2, o3);
    }
}

// ---------------- K6: layer-2 transforms (xl2, xr2, lin2) ----------------
__global__ void k_l2xform(const float* __restrict__ Wl2, const float* __restrict__ Wr2,
                          const float* __restrict__ Wlin2, const float* __restrict__ blin2) {
    __shared__ float Ws[384];  // [0:128) Wl2, [128:256) Wr2, [256:384) Wlin2
    int tid = threadIdx.x;
    Ws[tid] = Wl2[tid & 127];               // blockDim = 128
    Ws[128 + tid] = Wr2[tid & 127];
    Ws[256 + tid] = Wlin2[tid & 127];
    __syncthreads();
    int i = blockIdx.x * 128 + tid;
    if (i >= Nn) return;
    float al0 = 0, al1 = 0, ar0 = 0, ar1 = 0, an0 = 0, an1 = 0;
    const float4* h4 = (const float4*)(g_h + (size_t)i * 64);
#pragma unroll
    for (int q = 0; q < 16; q++) {
        float4 hv = h4[q];
        int k = q * 4;
        float c[4] = {hv.x, hv.y, hv.z, hv.w};
#pragma unroll
        for (int t = 0; t < 4; t++) {
            int kk = k + t;
            al0 += c[t] * Ws[2 * kk];       al1 += c[t] * Ws[2 * kk + 1];
            ar0 += c[t] * Ws[128 + 2 * kk]; ar1 += c[t] * Ws[128 + 2 * kk + 1];
            an0 += c[t] * Ws[256 + 2 * kk]; an1 += c[t] * Ws[256 + 2 * kk + 1];
        }
    }
    ((float2*)g_xl2)[i] = make_float2(al0, al1);
    ((float2*)g_xr2)[i] = make_float2(ar0, ar1);
    ((float2*)g_lin2)[i] = make_float2(an0 + blin2[0], an1 + blin2[1]);
}

// ---------------- K7: layer-2 attention, SINGLE PASS + log_softmax ----------------
__global__ void k_att2(const float* __restrict__ att2, const float* __restrict__ b2,
                       float* __restrict__ out) {
    int gt = blockIdx.x * blockDim.x + threadIdx.x;
    int i = gt >> 5;
    int lane = gt & 31;
    if (i >= Nn) return;

    int e0 = g_rowptr[i], e1 = g_rowptr[i + 1];
    const float2* xl2v = (const float2*)g_xl2;
    float2 xr = ((const float2*)g_xr2)[i];
    float a0 = att2[0], a1 = att2[1];

    float m = -1e30f, s = 0.f, A0 = 0.f, A1 = 0.f;
    for (int base = e0; base < e1; base += 32) {
        int idx = base + lane;
        if (idx < e1) {
            int j = g_col[idx];
            float2 xj = xl2v[j];
            float h0 = xj.x + xr.x; h0 = (h0 > 0.f) ? h0 : 0.2f * h0;
            float h1 = xj.y + xr.y; h1 = (h1 > 0.f) ? h1 : 0.2f * h1;
            float e = a0 * h0 + a1 * h1;
            if (e > m) { float sc = __expf(m - e); s *= sc; A0 *= sc; A1 *= sc; m = e; }
            float w = __expf(e - m);
            s += w; A0 += w * xj.x; A1 += w * xj.y;
        }
    }
    // merge lanes with rescale
#pragma unroll
    for (int o = 16; o; o >>= 1) {
        float mo  = __shfl_xor_sync(0xffffffffu, m, o);
        float so  = __shfl_xor_sync(0xffffffffu, s, o);
        float A0o = __shfl_xor_sync(0xffffffffu, A0, o);
        float A1o = __shfl_xor_sync(0xffffffffu, A1, o);
        float mn = fmaxf(m, mo);
        float sc1 = __expf(m - mn);
        float sc2 = __expf(mo - mn);
        s  = s * sc1 + so * sc2;
        A0 = A0 * sc1 + A0o * sc2;
        A1 = A1 * sc1 + A1o * sc2;
        m = mn;
    }

    if (lane == 0) {
        float inv = 1.0f / s;
        float2 ln = ((const float2*)g_lin2)[i];
        float z0 = A0 * inv + b2[0] + ln.x;
        float z1 = A1 * inv + b2[1] + ln.y;
        float zm = fmaxf(z0, z1);
        float l = zm + __logf(__expf(z0 - zm) + __expf(z1 - zm));
        ((float2*)out)[i] = make_float2(z0 - l, z1 - l);
    }
}

// ---------------- K8: edge_index passthrough as float32 values ----------------
__global__ void k_cast_edges(const int* __restrict__ ei, float* __restrict__ out, int n) {
    int i = blockIdx.x * blockDim.x + threadIdx.x;
    if (i < n) out[i] = (float)ei[i];
}

// ---------------- launcher: fork GEMM chain || CSR chain, join before att1 ----------------
extern "C" void kernel_launch(void* const* d_in, const int* in_sizes, int n_in,
                              void* d_out, int out_size) {
    const float* x        = (const float*)d_in[0];
    const float* Wl1      = (const float*)d_in[2];
    const float* Wr1      = (const float*)d_in[3];
    const float* att1     = (const float*)d_in[4];
    const float* b1       = (const float*)d_in[5];
    const float* Wlin1    = (const float*)d_in[6];
    const float* blin1    = (const float*)d_in[7];
    const float* Wl2      = (const float*)d_in[8];
    const float* Wr2      = (const float*)d_in[9];
    const float* att2     = (const float*)d_in[10];
    const float* b2       = (const float*)d_in[11];
    const float* Wlin2    = (const float*)d_in[12];
    const float* blin2    = (const float*)d_in[13];
    float* out = (float*)d_out;

    long long tail_elems = (long long)out_size - (long long)Nn * 2;

    cudaFuncSetAttribute(k_gemm1, cudaFuncAttributeMaxDynamicSharedMemorySize, G1_SMEM);

    int nb = (Nn + 1023) / 1024;   // 98

    // Fork a side stream for the GEMM (independent of CSR build).
    cudaStream_t s2;
    cudaStreamCreateWithFlags(&s2, cudaStreamNonBlocking);
    cudaEvent_t evFork, evJoin;
    cudaEventCreateWithFlags(&evFork, cudaEventDisableTiming);
    cudaEventCreateWithFlags(&evJoin, cudaEventDisableTiming);

    cudaEventRecord(evFork, 0);
    cudaStreamWaitEvent(s2, evFork, 0);

    // side stream: the big dense transform only (critical-path minimal)
    k_gemm1<<<152, G1_THREADS, G1_SMEM, s2>>>(x, Wl1, Wr1, Wlin1, blin1);
    cudaEventRecord(evJoin, s2);

    // main stream: CSR build chain, then output tail (both shadowed by gemm1)
    k_init_deg<<<(Nn + 255) / 256, 256>>>();
    k_deg<<<(Ee + 255) / 256, 256>>>((const int*)d_in[1]);
    k_scan1<<<nb, 1024>>>();
    k_scan2<<<1, 128>>>(nb);
    k_scan3<<<(Nn + 255) / 256, 256>>>();
    k_scatter<<<(ET + 255) / 256, 256>>>((const int*)d_in[1]);
    if (tail_elems > 0) {
        int n = (tail_elems < (long long)2 * Ee) ? (int)tail_elems : 2 * Ee;
        k_cast_edges<<<(n + 255) / 256, 256>>>(
            (const int*)d_in[1], out + (size_t)Nn * 2, n);
    }

    // join: attention needs both GEMM outputs and CSR
    cudaStreamWaitEvent(0, evJoin, 0);
    k_att1<<<(Nn * 32 + 255) / 256, 256>>>(att1, b1);
    k_l2xform<<<(Nn + 127) / 128, 128>>>(Wl2, Wr2, Wlin2, blin2);
    k_att2<<<(Nn * 32 + 255) / 256, 256>>>(att2, b2, out);

    cudaEventDestroy(evFork);
    cudaEventDestroy(evJoin);
    cudaStreamDestroy(s2);
}

// round 11
// speedup vs baseline: 1.4698x; 1.0058x over previous
#include <cuda_runtime.h>
#include <math.h>

// Problem constants (from reference)
constexpr int Nn  = 100000;
constexpr int Ee  = 3200000;
constexpr int ET  = Nn + Ee;       // edges + self loops
constexpr int FIN = 165;
constexpr int HID = 64;

// ---------------- scratch (static device allocations; no cudaMalloc) ----------------
__device__ float g_xl1[(size_t)Nn * HID];
__device__ float g_xr1[(size_t)Nn * HID];
__device__ float g_h  [(size_t)Nn * HID];   // x@Wlin1+blin1, then final layer-1 hidden
__device__ float g_xl2[Nn * 2];
__device__ float g_xr2[Nn * 2];
__device__ float g_lin2[Nn * 2];
__device__ int   g_deg[Nn];
__device__ int   g_incl[Nn];
__device__ int   g_rowptr[Nn + 1];
__device__ int   g_cursor[Nn];
__device__ int   g_bsum[128];
__device__ int   g_boff[128];
__device__ int   g_col[ET];

// Packed f32x2 FMA (Blackwell): acc = w * x + acc on a 64-bit register pair.
#define FMA2(acc, w, xp) \
    asm("fma.rn.f32x2 %0, %1, %2, %0;" : "+l"(acc) : "l"(w), "l"(xp))
#define PACK_DUP(xp, xv) \
    asm("mov.b64 %0, {%1, %1};" : "=l"(xp) : "f"(xv))
#define UNPACK2(lo, hi, p) \
    asm("mov.b64 {%0, %1}, %2;" : "=f"(lo), "=f"(hi) : "l"(p))

// ---------------- K0: init degrees (self loop => start at 1) ----------------
__global__ void k_init_deg() {
    int i = blockIdx.x * blockDim.x + threadIdx.x;
    if (i < Nn) g_deg[i] = 1;
}

// ---------------- K1: fused layer-1 triple GEMM (FFMA2 column-paired) ----------------
// xl1 = x@Wl1, xr1 = x@Wr1, h = x@Wlin1 + blin1.
// 64-node tiles, 4 nodes x 8 cols per thread; adjacent output columns packed
// into f32x2 pairs: 16 FFMA2 per k per thread (halves fma-pipe occupancy).
constexpr int G1_THREADS = 384;                 // 24 col-threads x 16 node-threads
constexpr int G1_SMEM = (FIN * 192 + 64 * FIN) * 4;   // 168,960 B

__global__ __launch_bounds__(G1_THREADS, 1)
void k_gemm1(const float* __restrict__ x,
             const float* __restrict__ Wl, const float* __restrict__ Wr,
             const float* __restrict__ Wlin, const float* __restrict__ blin) {
    extern __shared__ float sm[];
    float* Wsh = sm;                  // [165][192]
    float* Xsh = sm + FIN * 192;      // [64][165]
    int tid = threadIdx.x;

    for (int idx = tid; idx < FIN * 192; idx += G1_THREADS) {
        int k = idx / 192, c = idx % 192;
        float v = (c < 64) ? Wl[k * 64 + c]
                : (c < 128) ? Wr[k * 64 + (c - 64)]
                : Wlin[k * 64 + (c - 128)];
        Wsh[idx] = v;
    }
    __syncthreads();

    int ct = tid % 24;                // col group: 8 cols each
    int nt = tid / 24;                // node group: 4 nodes each (nt 0..15)
    int cbase = ct * 8;
    int region = cbase >> 6;          // 0: xl1, 1: xr1, 2: lin
    int coff = cbase & 63;

    float bias_r[8];
#pragma unroll
    for (int q = 0; q < 8; q++) bias_r[q] = (region == 2) ? blin[coff + q] : 0.0f;

    const ulonglong2* W2 = (const ulonglong2*)Wsh;   // 16B = 2 packed f32 pairs
    constexpr int NTILES = (Nn + 63) / 64;   // 1563 (last tile has 32 rows)

    for (int tile = blockIdx.x; tile < NTILES; tile += gridDim.x) {
        int row0 = tile * 64;
        int rows = (Nn - row0 < 64) ? (Nn - row0) : 64;
        const float4* xsrc = (const float4*)(x + (size_t)row0 * FIN);
        float4* xdst = (float4*)Xsh;
        int nload = (rows * FIN) / 4;
        for (int idx = tid; idx < nload; idx += G1_THREADS) xdst[idx] = xsrc[idx];
        __syncthreads();

        unsigned long long acc2[4][4];
#pragma unroll
        for (int n = 0; n < 4; n++)
#pragma unroll
            for (int q = 0; q < 4; q++) acc2[n][q] = 0ULL;

        const float* xr0 = Xsh + (nt * 4 + 0) * FIN;
        const float* xr1 = Xsh + (nt * 4 + 1) * FIN;
        const float* xr2 = Xsh + (nt * 4 + 2) * FIN;
        const float* xr3 = Xsh + (nt * 4 + 3) * FIN;

#pragma unroll 3
        for (int k = 0; k < FIN; k++) {
            unsigned long long xp0, xp1, xp2, xp3;
            PACK_DUP(xp0, xr0[k]);
            PACK_DUP(xp1, xr1[k]);
            PACK_DUP(xp2, xr2[k]);
            PACK_DUP(xp3, xr3[k]);
            ulonglong2 wA = W2[k * 48 + ct * 2];       // cols c0c1 | c2c3
            ulonglong2 wB = W2[k * 48 + ct * 2 + 1];   // cols c4c5 | c6c7
            FMA2(acc2[0][0], wA.x, xp0); FMA2(acc2[0][1], wA.y, xp0);
            FMA2(acc2[0][2], wB.x, xp0); FMA2(acc2[0][3], wB.y, xp0);
            FMA2(acc2[1][0], wA.x, xp1); FMA2(acc2[1][1], wA.y, xp1);
            FMA2(acc2[1][2], wB.x, xp1); FMA2(acc2[1][3], wB.y, xp1);
            FMA2(acc2[2][0], wA.x, xp2); FMA2(acc2[2][1], wA.y, xp2);
            FMA2(acc2[2][2], wB.x, xp2); FMA2(acc2[2][3], wB.y, xp2);
            FMA2(acc2[3][0], wA.x, xp3); FMA2(acc2[3][1], wA.y, xp3);
            FMA2(acc2[3][2], wB.x, xp3); FMA2(acc2[3][3], wB.y, xp3);
        }

#pragma unroll
        for (int n = 0; n < 4; n++) {
            int ng = row0 + nt * 4 + n;
            if (ng < Nn) {
                float a0, a1, a2, a3, a4, a5, a6, a7;
                UNPACK2(a0, a1, acc2[n][0]);
                UNPACK2(a2, a3, acc2[n][1]);
                UNPACK2(a4, a5, acc2[n][2]);
                UNPACK2(a6, a7, acc2[n][3]);
                float* base = (region == 0) ? g_xl1 : (region == 1) ? g_xr1 : g_h;
                base += (size_t)ng * 64 + coff;
                float4 v0 = make_float4(a0 + bias_r[0], a1 + bias_r[1],
                                        a2 + bias_r[2], a3 + bias_r[3]);
                float4 v1 = make_float4(a4 + bias_r[4], a5 + bias_r[5],
                                        a6 + bias_r[6], a7 + bias_r[7]);
                ((float4*)base)[0] = v0;
                ((float4*)base)[1] = v1;
            }
        }
        __syncthreads();
    }
}

// ---------------- K2: degree histogram over real edges ----------------
__global__ void k_deg(const int* __restrict__ ei) {
    int i = blockIdx.x * blockDim.x + threadIdx.x;
    if (i < Ee) {
        int d = ei[Ee + i];     // dst row
        atomicAdd(&g_deg[d], 1);
    }
}

// ---------------- K3: 3-phase exclusive scan -> rowptr, cursor ----------------
__global__ __launch_bounds__(1024) void k_scan1() {
    __shared__ int s[1024];
    int tid = threadIdx.x;
    int i = blockIdx.x * 1024 + tid;
    int v = (i < Nn) ? g_deg[i] : 0;
    s[tid] = v;
    __syncthreads();
    for (int off = 1; off < 1024; off <<= 1) {
        int t = (tid >= off) ? s[tid - off] : 0;
        __syncthreads();
        s[tid] += t;
        __syncthreads();
    }
    if (i < Nn) g_incl[i] = s[tid];
    if (tid == 1023) g_bsum[blockIdx.x] = s[tid];
}

__global__ void k_scan2(int nb) {
    __shared__ int s[128];
    int tid = threadIdx.x;
    int v = (tid < nb) ? g_bsum[tid] : 0;
    s[tid] = v;
    __syncthreads();
    for (int off = 1; off < 128; off <<= 1) {
        int t = (tid >= off) ? s[tid - off] : 0;
        __syncthreads();
        s[tid] += t;
        __syncthreads();
    }
    g_boff[tid] = s[tid] - v;   // exclusive
}

__global__ void k_scan3() {
    int i = blockIdx.x * blockDim.x + threadIdx.x;
    if (i < Nn) {
        int r = g_incl[i] + g_boff[i >> 10];
        g_rowptr[i + 1] = r;
        g_cursor[i] = r - g_deg[i];    // == rowptr[i]
        if (i == 0) g_rowptr[0] = 0;
    }
}

// ---------------- K4: scatter edges + self loops into CSR ----------------
__global__ void k_scatter(const int* __restrict__ ei) {
    int i = blockIdx.x * blockDim.x + threadIdx.x;
    if (i >= ET) return;
    int s, d;
    if (i < Ee) { s = ei[i]; d = ei[Ee + i]; }
    else        { s = d = i - Ee; }
    int pos = atomicAdd(&g_cursor[d], 1);
    g_col[pos] = s;
}

// ---------------- K5: layer-1 attention — half-warp slots (R9 version, measured best) ----------------
__global__ void k_att1(const float* __restrict__ att, const float* __restrict__ b1) {
    int gt = blockIdx.x * blockDim.x + threadIdx.x;
    int i = gt >> 5;
    int lane = gt & 31;
    if (i >= Nn) return;
    int half = lane >> 4;     // edge slot 0/1
    int g = lane & 15;        // channel group (4 channels)

    int e0 = g_rowptr[i], e1 = g_rowptr[i + 1];

    float4 r = ((const float4*)(g_xr1 + (size_t)i * 64))[g];
    float4 a = ((const float4*)att)[g];

    float m = -1e30f, s = 0.f;
    float A0 = 0.f, A1 = 0.f, A2 = 0.f, A3 = 0.f;

    for (int base = e0; base < e1; base += 2) {
        int idx = base + half;
        bool act = idx < e1;
        int j = act ? g_col[idx] : 0;
        float4 u = ((const float4*)(g_xl1 + (size_t)j * 64))[g];

        float t0 = u.x + r.x; t0 = (t0 > 0.f) ? t0 : 0.2f * t0;
        float t1 = u.y + r.y; t1 = (t1 > 0.f) ? t1 : 0.2f * t1;
        float t2 = u.z + r.z; t2 = (t2 > 0.f) ? t2 : 0.2f * t2;
        float t3 = u.w + r.w; t3 = (t3 > 0.f) ? t3 : 0.2f * t3;
        float p = t0 * a.x + t1 * a.y + t2 * a.z + t3 * a.w;
        // reduce within the 16-lane half (xor 1,2,4,8 keeps bit 4)
        p += __shfl_xor_sync(0xffffffffu, p, 1);
        p += __shfl_xor_sync(0xffffffffu, p, 2);
        p += __shfl_xor_sync(0xffffffffu, p, 4);
        p += __shfl_xor_sync(0xffffffffu, p, 8);

        if (act) {
            if (p > m) {
                float sc = __expf(m - p);
                s *= sc; A0 *= sc; A1 *= sc; A2 *= sc; A3 *= sc;
                m = p;
            }
            float w = __expf(p - m);
            s += w;
            A0 += w * u.x; A1 += w * u.y; A2 += w * u.z; A3 += w * u.w;
        }
    }

    // merge the two half-states (xor 16; same g, other half)
    {
        float mo  = __shfl_xor_sync(0xffffffffu, m, 16);
        float so  = __shfl_xor_sync(0xffffffffu, s, 16);
        float B0  = __shfl_xor_sync(0xffffffffu, A0, 16);
        float B1  = __shfl_xor_sync(0xffffffffu, A1, 16);
        float B2  = __shfl_xor_sync(0xffffffffu, A2, 16);
        float B3  = __shfl_xor_sync(0xffffffffu, A3, 16);
        float mn = fmaxf(m, mo);
        float c1 = __expf(m - mn);
        float c2 = __expf(mo - mn);
        s  = s * c1 + so * c2;
        A0 = A0 * c1 + B0 * c2;
        A1 = A1 * c1 + B1 * c2;
        A2 = A2 * c1 + B2 * c2;
        A3 = A3 * c1 + B3 * c2;
        m = mn;
    }

    if (half == 0) {
        float inv = 1.0f / s;
        float4 bb = ((const float4*)b1)[g];
        float4* h4 = (float4*)(g_h + (size_t)i * 64);
        float4 hl = h4[g];
        float o0 = A0 * inv + bb.x + hl.x;
        float o1 = A1 * inv + bb.y + hl.y;
        float o2 = A2 * inv + bb.z + hl.z;
        float o3 = A3 * inv + bb.w + hl.w;
        o0 = (o0 > 0.f) ? o0 : (__expf(o0) - 1.0f);   // ELU
        o1 = (o1 > 0.f) ? o1 : (__expf(o1) - 1.0f);
        o2 = (o2 > 0.f) ? o2 : (__expf(o2) - 1.0f);
        o3 = (o3 > 0.f) ? o3 : (__expf(o3) - 1.0f);
        h4[g] = make_float4(o0, o1, o2, o3);
    }
}

// ---------------- K6: layer-2 transforms (xl2, xr2, lin2) ----------------
__global__ void k_l2xform(const float* __restrict__ Wl2, const float* __restrict__ Wr2,
                          const float* __restrict__ Wlin2, const float* __restrict__ blin2) {
    __shared__ float Ws[384];  // [0:128) Wl2, [128:256) Wr2, [256:384) Wlin2
    int tid = threadIdx.x;
    Ws[tid] = Wl2[tid & 127];               // blockDim = 128
    Ws[128 + tid] = Wr2[tid & 127];
    Ws[256 + tid] = Wlin2[tid & 127];
    __syncthreads();
    int i = blockIdx.x * 128 + tid;
    if (i >= Nn) return;
    float al0 = 0, al1 = 0, ar0 = 0, ar1 = 0, an0 = 0, an1 = 0;
    const float4* h4 = (const float4*)(g_h + (size_t)i * 64);
#pragma unroll
    for (int q = 0; q < 16; q++) {
        float4 hv = h4[q];
        int k = q * 4;
        float c[4] = {hv.x, hv.y, hv.z, hv.w};
#pragma unroll
        for (int t = 0; t < 4; t++) {
            int kk = k + t;
            al0 += c[t] * Ws[2 * kk];       al1 += c[t] * Ws[2 * kk + 1];
            ar0 += c[t] * Ws[128 + 2 * kk]; ar1 += c[t] * Ws[128 + 2 * kk + 1];
            an0 += c[t] * Ws[256 + 2 * kk]; an1 += c[t] * Ws[256 + 2 * kk + 1];
        }
    }
    ((float2*)g_xl2)[i] = make_float2(al0, al1);
    ((float2*)g_xr2)[i] = make_float2(ar0, ar1);
    ((float2*)g_lin2)[i] = make_float2(an0 + blin2[0], an1 + blin2[1]);
}

// ---------------- K7: layer-2 attention, SINGLE PASS + log_softmax ----------------
__global__ void k_att2(const float* __restrict__ att2, const float* __restrict__ b2,
                       float* __restrict__ out) {
    int gt = blockIdx.x * blockDim.x + threadIdx.x;
    int i = gt >> 5;
    int lane = gt & 31;
    if (i >= Nn) return;

    int e0 = g_rowptr[i], e1 = g_rowptr[i + 1];
    const float2* xl2v = (const float2*)g_xl2;
    float2 xr = ((const float2*)g_xr2)[i];
    float a0 = att2[0], a1 = att2[1];

    float m = -1e30f, s = 0.f, A0 = 0.f, A1 = 0.f;
    for (int base = e0; base < e1; base += 32) {
        int idx = base + lane;
        if (idx < e1) {
            int j = g_col[idx];
            float2 xj = xl2v[j];
            float h0 = xj.x + xr.x; h0 = (h0 > 0.f) ? h0 : 0.2f * h0;
            float h1 = xj.y + xr.y; h1 = (h1 > 0.f) ? h1 : 0.2f * h1;
            float e = a0 * h0 + a1 * h1;
            if (e > m) { float sc = __expf(m - e); s *= sc; A0 *= sc; A1 *= sc; m = e; }
            float w = __expf(e - m);
            s += w; A0 += w * xj.x; A1 += w * xj.y;
        }
    }
    // merge lanes with rescale
#pragma unroll
    for (int o = 16; o; o >>= 1) {
        float mo  = __shfl_xor_sync(0xffffffffu, m, o);
        float so  = __shfl_xor_sync(0xffffffffu, s, o);
        float A0o = __shfl_xor_sync(0xffffffffu, A0, o);
        float A1o = __shfl_xor_sync(0xffffffffu, A1, o);
        float mn = fmaxf(m, mo);
        float sc1 = __expf(m - mn);
        float sc2 = __expf(mo - mn);
        s  = s * sc1 + so * sc2;
        A0 = A0 * sc1 + A0o * sc2;
        A1 = A1 * sc1 + A1o * sc2;
        m = mn;
    }

    if (lane == 0) {
        float inv = 1.0f / s;
        float2 ln = ((const float2*)g_lin2)[i];
        float z0 = A0 * inv + b2[0] + ln.x;
        float z1 = A1 * inv + b2[1] + ln.y;
        float zm = fmaxf(z0, z1);
        float l = zm + __logf(__expf(z0 - zm) + __expf(z1 - zm));
        ((float2*)out)[i] = make_float2(z0 - l, z1 - l);
    }
}

// ---------------- K8: edge_index passthrough as float32 values ----------------
__global__ void k_cast_edges(const int* __restrict__ ei, float* __restrict__ out, int n) {
    int i = blockIdx.x * blockDim.x + threadIdx.x;
    if (i < n) out[i] = (float)ei[i];
}

// ---------------- launcher: fork GEMM chain || CSR chain, join before att1 ----------------
extern "C" void kernel_launch(void* const* d_in, const int* in_sizes, int n_in,
                              void* d_out, int out_size) {
    const float* x        = (const float*)d_in[0];
    const float* Wl1      = (const float*)d_in[2];
    const float* Wr1      = (const float*)d_in[3];
    const float* att1     = (const float*)d_in[4];
    const float* b1       = (const float*)d_in[5];
    const float* Wlin1    = (const float*)d_in[6];
    const float* blin1    = (const float*)d_in[7];
    const float* Wl2      = (const float*)d_in[8];
    const float* Wr2      = (const float*)d_in[9];
    const float* att2     = (const float*)d_in[10];
    const float* b2       = (const float*)d_in[11];
    const float* Wlin2    = (const float*)d_in[12];
    const float* blin2    = (const float*)d_in[13];
    float* out = (float*)d_out;

    long long tail_elems = (long long)out_size - (long long)Nn * 2;

    cudaFuncSetAttribute(k_gemm1, cudaFuncAttributeMaxDynamicSharedMemorySize, G1_SMEM);

    int nb = (Nn + 1023) / 1024;   // 98

    // Fork a side stream for the GEMM (independent of CSR build).
    cudaStream_t s2;
    cudaStreamCreateWithFlags(&s2, cudaStreamNonBlocking);
    cudaEvent_t evFork, evJoin;
    cudaEventCreateWithFlags(&evFork, cudaEventDisableTiming);
    cudaEventCreateWithFlags(&evJoin, cudaEventDisableTiming);

    cudaEventRecord(evFork, 0);
    cudaStreamWaitEvent(s2, evFork, 0);

    // side stream: the big dense transform only (critical-path minimal)
    k_gemm1<<<152, G1_THREADS, G1_SMEM, s2>>>(x, Wl1, Wr1, Wlin1, blin1);
    cudaEventRecord(evJoin, s2);

    // main stream: CSR build chain, then output tail (both shadowed by gemm1)
    k_init_deg<<<(Nn + 255) / 256, 256>>>();
    k_deg<<<(Ee + 255) / 256, 256>>>((const int*)d_in[1]);
    k_scan1<<<nb, 1024>>>();
    k_scan2<<<1, 128>>>(nb);
    k_scan3<<<(Nn + 255) / 256, 256>>>();
    k_scatter<<<(ET + 255) / 256, 256>>>((const int*)d_in[1]);
    if (tail_elems > 0) {
        int n = (tail_elems < (long long)2 * Ee) ? (int)tail_elems : 2 * Ee;
        k_cast_edges<<<(n + 255) / 256, 256>>>(
            (const int*)d_in[1], out + (size_t)Nn * 2, n);
    }

    // join: attention needs both GEMM outputs and CSR
    cudaStreamWaitEvent(0, evJoin, 0);
    k_att1<<<(Nn * 32 + 255) / 256, 256>>>(att1, b1);
    k_l2xform<<<(Nn + 127) / 128, 128>>>(Wl2, Wr2, Wlin2, blin2);
    k_att2<<<(Nn * 32 + 255) / 256, 256>>>(att2, b2, out);

    cudaEventDestroy(evFork);
    cudaEventDestroy(evJoin);
    cudaStreamDestroy(s2);
}